// round 12
// baseline (speedup 1.0000x reference)
#include <cuda_runtime.h>
#include <cuda_bf16.h>
#include <cstdint>

#define DD 128
#define MAXN 50000
#define GG 64

// ---------------- device scratch ----------------
__device__ float g_h[(size_t)MAXN * DD];
__device__ float g_agg[(size_t)MAXN * DD];
__device__ float g_t[(size_t)MAXN * DD];
__device__ float g_sums[GG * DD];
__device__ float g_sq[GG * DD];
__device__ int   g_cnt[GG];
__device__ int   g_is64;
// W in mma B-fragment order: [(ks*8+nbp)*32+lane] -> uint4(b0,b1,b2,b3)
__device__ __align__(16) uint4 g_wfe_hi[2048];   // edge lin hi
__device__ __align__(16) uint4 g_wfe_lo[2048];   // edge lin lo
__device__ __align__(16) uint4 g_wf1_hi[2048];   // node lin1 hi
__device__ __align__(16) uint4 g_wf1_lo[2048];   // node lin1 lo

__device__ __forceinline__ long long ld_idx(const void* p, long long i, int is64) {
    return is64 ? ((const long long*)p)[i] : (long long)((const int*)p)[i];
}
__device__ __forceinline__ float silu_f(float x) { return x / (1.0f + __expf(-x)); }

__device__ __forceinline__ uint32_t smem_u32(const void* p) {
    uint32_t a;
    asm("{ .reg .u64 t; cvta.to.shared.u64 t, %1; cvt.u32.u64 %0, t; }" : "=r"(a) : "l"(p));
    return a;
}
__device__ __forceinline__ void mma_bf16(float* d, const uint32_t* a,
                                         uint32_t b0, uint32_t b1) {
    asm volatile("mma.sync.aligned.m16n8k16.row.col.f32.bf16.bf16.f32 "
                 "{%0,%1,%2,%3}, {%4,%5,%6,%7}, {%8,%9}, {%0,%1,%2,%3};"
                 : "+f"(d[0]), "+f"(d[1]), "+f"(d[2]), "+f"(d[3])
                 : "r"(a[0]), "r"(a[1]), "r"(a[2]), "r"(a[3]), "r"(b0), "r"(b1));
}
__device__ __forceinline__ uint32_t pack_bf16x2(float x, float y) {
    __nv_bfloat16 bx = __float2bfloat16(x), by = __float2bfloat16(y);
    return (uint32_t)__bfloat16_as_ushort(bx) | ((uint32_t)__bfloat16_as_ushort(by) << 16);
}
__device__ __forceinline__ uint32_t pack_hi2(float x, float y) {
    return pack_bf16x2(x, y);
}
__device__ __forceinline__ uint32_t pack_lo2(float x, float y) {
    float hx = __bfloat162float(__float2bfloat16(x));
    float hy = __bfloat162float(__float2bfloat16(y));
    return pack_bf16x2(x - hx, y - hy);
}

// ---------------- misc kernels ----------------
__global__ void k_detect(const unsigned* __restrict__ ei) {
    int all0 = 1;
    for (int i = 0; i < 64; i++) all0 &= (ei[2 * i + 1] == 0u);
    g_is64 = all0;
}

__global__ void k_zero(int Nn) {
    long long i = (long long)blockIdx.x * blockDim.x + threadIdx.x;
    long long step = (long long)gridDim.x * blockDim.x;
    long long tot = (long long)Nn * DD;
    for (long long k = i; k < tot; k += step) g_agg[k] = 0.f;
    for (long long k = i; k < GG * DD; k += step) { g_sums[k] = 0.f; g_sq[k] = 0.f; }
    if (i < GG) g_cnt[(int)i] = 0;
}

// Build W fragments from the mma.sync B-fragment mapping:
// frag fi = ks*8+nbp, lane L:
//   b0 = W[n0  ][k0..k0+1]   (n0 = nbp*16 + (L>>2), k0 = ks*16 + 2*(L&3))
//   b1 = W[n0+8][k0..k0+1], b2 = W[n0][k0+8..], b3 = W[n0+8][k0+8..]
__global__ void k_prep_w(const float* __restrict__ We, const float* __restrict__ W1) {
    int tid = blockIdx.x * blockDim.x + threadIdx.x;   // 0..2047
    if (tid >= 2048) return;
    int fi = tid >> 5, lane = tid & 31;
    int ks = fi >> 3, nbp = fi & 7;
    int n0 = nbp * 16 + (lane >> 2);
    int k0 = ks * 16 + 2 * (lane & 3);
    {
        float2 w00 = *(const float2*)(We + n0 * DD + k0);
        float2 w10 = *(const float2*)(We + (n0 + 8) * DD + k0);
        float2 w01 = *(const float2*)(We + n0 * DD + k0 + 8);
        float2 w11 = *(const float2*)(We + (n0 + 8) * DD + k0 + 8);
        g_wfe_hi[tid] = make_uint4(pack_hi2(w00.x, w00.y), pack_hi2(w10.x, w10.y),
                                   pack_hi2(w01.x, w01.y), pack_hi2(w11.x, w11.y));
        g_wfe_lo[tid] = make_uint4(pack_lo2(w00.x, w00.y), pack_lo2(w10.x, w10.y),
                                   pack_lo2(w01.x, w01.y), pack_lo2(w11.x, w11.y));
    }
    {
        float2 w00 = *(const float2*)(W1 + n0 * DD + k0);
        float2 w10 = *(const float2*)(W1 + (n0 + 8) * DD + k0);
        float2 w01 = *(const float2*)(W1 + n0 * DD + k0 + 8);
        float2 w11 = *(const float2*)(W1 + (n0 + 8) * DD + k0 + 8);
        g_wf1_hi[tid] = make_uint4(pack_hi2(w00.x, w00.y), pack_hi2(w10.x, w10.y),
                                   pack_hi2(w01.x, w01.y), pack_hi2(w11.x, w11.y));
        g_wf1_lo[tid] = make_uint4(pack_lo2(w00.x, w00.y), pack_lo2(w10.x, w10.y),
                                   pack_lo2(w01.x, w01.y), pack_lo2(w11.x, w11.y));
    }
}

// ---------------- shared mma-tile machinery ----------------
// smem: D staging only, [128][DSTR] floats -> 67.6KB -> 2 CTAs/SM
#define DSTR 132
#define SM_TILE_TOTAL (128 * DSTR * 4)

// A fragments are loaded straight from global (each element read once per CTA).
// OOB rows are clamped (garbage OK: D rows map 1:1 to A rows and the epilogue
// discards invalid rows).
__device__ __forceinline__ void tile_gemm_stage(char* smem,
                                                const float* __restrict__ X,
                                                const uint4* __restrict__ Wfhi,
                                                const uint4* __restrict__ Wflo,
                                                long long r0, long long rows, int tid) {
    int wid = tid >> 5, lane = tid & 31;

    float acc[16][4];
#pragma unroll
    for (int i = 0; i < 16; i++)
#pragma unroll
        for (int j = 0; j < 4; j++) acc[i][j] = 0.f;

    long long ra = r0 + wid * 16 + (lane >> 2);
    long long rb = ra + 8;
    if (ra >= rows) ra = rows - 1;
    if (rb >= rows) rb = rows - 1;
    int kcol = 2 * (lane & 3);
    const float* A0 = X + ra * DD + kcol;
    const float* A1 = X + rb * DD + kcol;

    float2 x0 = *(const float2*)(A0);
    float2 x1 = *(const float2*)(A1);
    float2 x2 = *(const float2*)(A0 + 8);
    float2 x3 = *(const float2*)(A1 + 8);

#pragma unroll 1
    for (int ks = 0; ks < 8; ks++) {
        float2 n0, n1, n2, n3;
        if (ks < 7) {
            int kb = (ks + 1) * 16;
            n0 = *(const float2*)(A0 + kb);
            n1 = *(const float2*)(A1 + kb);
            n2 = *(const float2*)(A0 + kb + 8);
            n3 = *(const float2*)(A1 + kb + 8);
        }
        uint32_t ahi[4] = { pack_hi2(x0.x, x0.y), pack_hi2(x1.x, x1.y),
                            pack_hi2(x2.x, x2.y), pack_hi2(x3.x, x3.y) };
        uint32_t alo[4] = { pack_lo2(x0.x, x0.y), pack_lo2(x1.x, x1.y),
                            pack_lo2(x2.x, x2.y), pack_lo2(x3.x, x3.y) };
        const uint4* wph = Wfhi + ks * 256 + lane;
        const uint4* wpl = Wflo + ks * 256 + lane;
#pragma unroll
        for (int nbp = 0; nbp < 8; nbp++) {
            uint4 bh = wph[nbp * 32];
            uint4 bl = wpl[nbp * 32];
            mma_bf16(acc[2 * nbp], ahi, bh.x, bh.z);
            mma_bf16(acc[2 * nbp + 1], ahi, bh.y, bh.w);
            mma_bf16(acc[2 * nbp], ahi, bl.x, bl.z);
            mma_bf16(acc[2 * nbp + 1], ahi, bl.y, bl.w);
            mma_bf16(acc[2 * nbp], alo, bh.x, bh.z);
            mma_bf16(acc[2 * nbp + 1], alo, bh.y, bh.w);
        }
        x0 = n0; x1 = n1; x2 = n2; x3 = n3;
    }

    // stage D
    float* Ds = (float*)smem;
    {
        int rbr = wid * 16 + (lane >> 2);
        int cb = (lane & 3) * 2;
#pragma unroll
        for (int nb = 0; nb < 16; nb++) {
            *(float2*)&Ds[rbr * DSTR + nb * 8 + cb] = make_float2(acc[nb][0], acc[nb][1]);
            *(float2*)&Ds[(rbr + 8) * DSTR + nb * 8 + cb] = make_float2(acc[nb][2], acc[nb][3]);
        }
    }
    __syncthreads();
}

// ---------------- node lin1 via mma ----------------
__global__ __launch_bounds__(256, 2) void k_node_mma(const float* __restrict__ X,
                                                     const float* __restrict__ bias,
                                                     int Nn) {
    extern __shared__ char smem[];
    int tid = threadIdx.x;
    long long r0 = (long long)blockIdx.x * 128;
    tile_gemm_stage(smem, X, g_wf1_hi, g_wf1_lo, r0, Nn, tid);

    float* Ds = (float*)smem;
    int row = tid >> 1, ch = (tid & 1) * 64;
    long long r = r0 + row;
    if (r < Nn) {
        const float* bp = bias + ch;
        float* op = g_h + r * DD + ch;
#pragma unroll
        for (int j = 0; j < 16; j++) {
            float4 dv = *(const float4*)&Ds[row * DSTR + ch + j * 4];
            float4 bb = *(const float4*)(bp + j * 4);
            *(float4*)(op + j * 4) = make_float4(dv.x + bb.x, dv.y + bb.y,
                                                 dv.z + bb.z, dv.w + bb.w);
        }
    }
}

// ---------------- edge kernel via mma + vector atomics ----------------
__global__ __launch_bounds__(256, 2) void k_edge_mma(const float* __restrict__ EA,
                                                     const float* __restrict__ bias,
                                                     const void* __restrict__ ei,
                                                     int Ee) {
    extern __shared__ char smem[];
    int tid = threadIdx.x;
    long long r0 = (long long)blockIdx.x * 128;

    // hoist edge indices (L2-resident) before tile work
    int row = tid >> 1, ch = (tid & 1) * 64;
    long long e = r0 + row;
    long long s = 0, d = 0;
    int valid = (e < Ee);
    if (valid) {
        int is64 = g_is64;
        s = ld_idx(ei, e, is64);
        d = ld_idx(ei, (long long)Ee + e, is64);
    }

    tile_gemm_stage(smem, EA, g_wfe_hi, g_wfe_lo, r0, Ee, tid);

    float* Ds = (float*)smem;
    if (valid) {
        const float* hp = g_h + s * DD + ch;
        const float* bp = bias + ch;
        float4* ap = (float4*)(g_agg + d * DD + ch);
#pragma unroll
        for (int j = 0; j < 16; j++) {
            float4 dv = *(const float4*)&Ds[row * DSTR + ch + j * 4];
            float4 hv = *(const float4*)(hp + j * 4);
            float4 bb = *(const float4*)(bp + j * 4);
            float4 m;
            m.x = silu_f(dv.x + bb.x + hv.x);
            m.y = silu_f(dv.y + bb.y + hv.y);
            m.z = silu_f(dv.z + bb.z + hv.z);
            m.w = silu_f(dv.w + bb.w + hv.w);
            atomicAdd(ap + j, m);   // 128-bit RED
        }
    }
}

// ---------------- post kernels (GraphNorm) ----------------
__global__ void k_post1(const float* __restrict__ X, const void* __restrict__ batch,
                        const float* __restrict__ epsp, int Nn) {
    int c = threadIdx.x & 127;
    int half = threadIdx.x >> 7;
    long long n0 = (long long)blockIdx.x * 64 + half * 32;
    float ep = 1.0f + epsp[0];
    int is64 = g_is64;
    int curg = -1; float accv = 0.f; int cr = 0;
    for (int q = 0; q < 32; q++) {
        long long n = n0 + q;
        if (n >= Nn) break;
        long long off = n * DD + c;
        float conv = ep * g_h[off] + g_agg[off];
        float t = silu_f(conv) + X[off];
        g_t[off] = t;
        int g = (int)ld_idx(batch, n, is64);
        if (g != curg) {
            if (curg >= 0) {
                atomicAdd(&g_sums[curg * DD + c], accv);
                if (c == 0) atomicAdd(&g_cnt[curg], cr);
            }
            curg = g; accv = t; cr = 1;
        } else { accv += t; cr++; }
    }
    if (curg >= 0) {
        atomicAdd(&g_sums[curg * DD + c], accv);
        if (c == 0) atomicAdd(&g_cnt[curg], cr);
    }
}

__global__ void k_post2(const void* __restrict__ batch, const float* __restrict__ gms,
                        int Nn) {
    int c = threadIdx.x & 127;
    int half = threadIdx.x >> 7;
    long long n0 = (long long)blockIdx.x * 64 + half * 32;
    int is64 = g_is64;
    float msc = gms[c];
    int curg = -1; float mean = 0.f, ssq = 0.f;
    for (int q = 0; q < 32; q++) {
        long long n = n0 + q;
        if (n >= Nn) break;
        int g = (int)ld_idx(batch, n, is64);
        if (g != curg) {
            if (curg >= 0) atomicAdd(&g_sq[curg * DD + c], ssq);
            curg = g; ssq = 0.f;
            float cf = fmaxf((float)g_cnt[g], 1.f);
            mean = g_sums[g * DD + c] / cf;
        }
        long long off = n * DD + c;
        float o = g_t[off] - mean * msc;
        g_h[off] = o;
        ssq += o * o;
    }
    if (curg >= 0) atomicAdd(&g_sq[curg * DD + c], ssq);
}

__global__ void k_post3(const void* __restrict__ batch, const float* __restrict__ gw,
                        const float* __restrict__ gb, float* __restrict__ out, int Nn) {
    long long i = (long long)blockIdx.x * blockDim.x + threadIdx.x;
    long long step = (long long)gridDim.x * blockDim.x;
    long long tot = (long long)Nn * DD;
    int is64 = g_is64;
    for (long long k = i; k < tot; k += step) {
        long long n = k >> 7;
        int c = (int)(k & 127);
        int g = (int)ld_idx(batch, n, is64);
        float cf = fmaxf((float)g_cnt[g], 1.f);
        float stdv = sqrtf(g_sq[g * DD + c] / cf + 1e-5f);
        out[k] = gw[c] * g_h[k] / stdv + gb[c];
    }
}

// ---------------- launcher ----------------
extern "C" void kernel_launch(void* const* d_in, const int* in_sizes, int n_in,
                              void* d_out, int out_size) {
    const float* node_h    = (const float*)d_in[0];
    const float* edge_attr = (const float*)d_in[1];
    const void*  batch     = d_in[2];
    const void*  ei        = d_in[3];
    const float* w1  = (const float*)d_in[4];
    const float* b1  = (const float*)d_in[5];
    const float* we  = (const float*)d_in[6];
    const float* be  = (const float*)d_in[7];
    const float* eps = (const float*)d_in[8];
    const float* gnw = (const float*)d_in[9];
    const float* gnb = (const float*)d_in[10];
    const float* gms = (const float*)d_in[11];

    int Nn = in_sizes[0] / DD;
    int Ee = in_sizes[1] / DD;

    cudaFuncSetAttribute(k_node_mma, cudaFuncAttributeMaxDynamicSharedMemorySize,
                         SM_TILE_TOTAL);
    cudaFuncSetAttribute(k_edge_mma, cudaFuncAttributeMaxDynamicSharedMemorySize,
                         SM_TILE_TOTAL);

    k_detect<<<1, 1>>>((const unsigned*)ei);
    k_zero<<<1024, 256>>>(Nn);
    k_prep_w<<<8, 256>>>(we, w1);
    k_node_mma<<<(Nn + 127) / 128, 256, SM_TILE_TOTAL>>>(node_h, b1, Nn);
    k_edge_mma<<<(Ee + 127) / 128, 256, SM_TILE_TOTAL>>>(edge_attr, be, ei, Ee);
    k_post1<<<(Nn + 63) / 64, 256>>>(node_h, batch, eps, Nn);
    k_post2<<<(Nn + 63) / 64, 256>>>(batch, gms, Nn);
    k_post3<<<2048, 256>>>(batch, gnw, gnb, (float*)d_out, Nn);
}